// round 7
// baseline (speedup 1.0000x reference)
#include <cuda_runtime.h>
#include <cuda_bf16.h>

#define CW    32            // context window
#define DDIM  512           // embedding dim
#define NTHR  128           // 4 warps per CTA, one CTA per batch row
#define NW    4             // warps per CTA
#define CPW   (CW / NW)     // context rows per warp = 8

// Lane l owns dims { i*128 + l*4 .. +4 } for i in 0..3  (coalesced, conflict-free)

__global__ __launch_bounds__(NTHR, 6)
void kre_kernel(const int* __restrict__ context,
                const int* __restrict__ center,
                const float* __restrict__ W,
                float* __restrict__ out)
{
    __shared__ float s_acc[NW * DDIM];   // per-warp partial outputs (8 KB)
    __shared__ float s_wsum[NW];
    __shared__ int   s_idx[CW];

    const int b    = blockIdx.x;
    const int tid  = threadIdx.x;
    const int lane = tid & 31;
    const int warp = tid >> 5;

    if (tid < CW) s_idx[tid] = context[b * CW + tid];
    __syncthreads();

    // Center row slice for this lane (kept in registers for all rows)
    const float4* cen_p = (const float4*)(W + (size_t)center[b] * DDIM) + lane;
    float4 cen[4];
    #pragma unroll
    for (int i = 0; i < 4; ++i) cen[i] = cen_p[i * 32];

    float4 acc[4];
    #pragma unroll
    for (int i = 0; i < 4; ++i) acc[i] = make_float4(0.f, 0.f, 0.f, 0.f);
    float wsum = 0.f;

    // Each warp: 8 context rows, processed TWO at a time so the two
    // 5-deep shuffle-reduction chains (~130 cyc each) pipeline instead of
    // serializing, and 32 LDG.128 are in flight per iteration.
    #pragma unroll
    for (int cc = 0; cc < CPW; cc += 2) {
        const float4* p0 = (const float4*)(W + (size_t)s_idx[warp * CPW + cc]     * DDIM) + lane;
        const float4* p1 = (const float4*)(W + (size_t)s_idx[warp * CPW + cc + 1] * DDIM) + lane;

        float4 v0[4], v1[4];
        #pragma unroll
        for (int i = 0; i < 4; ++i) v0[i] = p0[i * 32];
        #pragma unroll
        for (int i = 0; i < 4; ++i) v1[i] = p1[i * 32];

        float d0 = 0.f, d1 = 0.f;
        #pragma unroll
        for (int i = 0; i < 4; ++i) {
            float ax = v0[i].x - cen[i].x, ay = v0[i].y - cen[i].y;
            float az = v0[i].z - cen[i].z, aw = v0[i].w - cen[i].w;
            d0 = fmaf(ax, ax, d0); d0 = fmaf(ay, ay, d0);
            d0 = fmaf(az, az, d0); d0 = fmaf(aw, aw, d0);
            float bx = v1[i].x - cen[i].x, by = v1[i].y - cen[i].y;
            float bz = v1[i].z - cen[i].z, bw = v1[i].w - cen[i].w;
            d1 = fmaf(bx, bx, d1); d1 = fmaf(by, by, d1);
            d1 = fmaf(bz, bz, d1); d1 = fmaf(bw, bw, d1);
        }

        // Interleaved, independent butterflies — chains overlap in the pipe
        #pragma unroll
        for (int off = 16; off > 0; off >>= 1) {
            d0 += __shfl_xor_sync(0xffffffffu, d0, off);
            d1 += __shfl_xor_sync(0xffffffffu, d1, off);
        }

        const float w0 = __expf(-0.5f * d0);   // SIGMA = 1; exact 1.0 at d==0
        const float w1 = __expf(-0.5f * d1);
        wsum += w0 + w1;

        #pragma unroll
        for (int i = 0; i < 4; ++i) {
            acc[i].x = fmaf(w0, v0[i].x, acc[i].x);
            acc[i].y = fmaf(w0, v0[i].y, acc[i].y);
            acc[i].z = fmaf(w0, v0[i].z, acc[i].z);
            acc[i].w = fmaf(w0, v0[i].w, acc[i].w);
            acc[i].x = fmaf(w1, v1[i].x, acc[i].x);
            acc[i].y = fmaf(w1, v1[i].y, acc[i].y);
            acc[i].z = fmaf(w1, v1[i].z, acc[i].z);
            acc[i].w = fmaf(w1, v1[i].w, acc[i].w);
        }
    }

    // Spill per-warp partials (lane stride 16 B -> conflict-free)
    #pragma unroll
    for (int i = 0; i < 4; ++i)
        *(float4*)(s_acc + warp * DDIM + i * 128 + lane * 4) = acc[i];
    if (lane == 0) s_wsum[warp] = wsum;   // wgt broadcast => wsum lane-uniform
    __syncthreads();

    // Combine 4 warp partials; normalize once at the end (same math as ref)
    const float inv = 1.0f / (s_wsum[0] + s_wsum[1] + s_wsum[2] + s_wsum[3] + 1e-8f);

    float4 r = make_float4(0.f, 0.f, 0.f, 0.f);
    #pragma unroll
    for (int w = 0; w < NW; ++w) {
        const float4 p = *(const float4*)(s_acc + w * DDIM + tid * 4);
        r.x += p.x; r.y += p.y; r.z += p.z; r.w += p.w;
    }
    r.x *= inv; r.y *= inv; r.z *= inv; r.w *= inv;
    // Streaming write-through: don't let the 16 MB output evict W from L2.
    __stwt((float4*)(out + (size_t)b * DDIM + tid * 4), r);
}

extern "C" void kernel_launch(void* const* d_in, const int* in_sizes, int n_in,
                              void* d_out, int out_size)
{
    const int*   context = (const int*)d_in[0];   // [B, C] int32
    const int*   center  = (const int*)d_in[1];   // [B]    int32
    const float* W       = (const float*)d_in[2]; // [V, D] float32
    float*       out     = (float*)d_out;         // [B, D] float32

    const int B = in_sizes[1];                    // 8192

    kre_kernel<<<B, NTHR>>>(context, center, W, out);
}

// round 10
// speedup vs baseline: 1.0287x; 1.0287x over previous
#include <cuda_runtime.h>
#include <cuda_bf16.h>
#include <cstdint>

#define CW    32            // context window
#define DDIM  512           // embedding dim
#define NTHR  128           // 4 warps per CTA, one CTA per batch row
#define NW    4             // warps per CTA
#define CPW   (CW / NW)     // context rows per warp = 8
#define S     3             // cp.async pipeline depth (rows in flight per warp)

// Lane l owns dims { i*128 + l*4 .. +4 } for i in 0..3  (coalesced, conflict-free)

__device__ __forceinline__ void cp16(unsigned int saddr, const void* gptr, int szbytes) {
    // cp.async with src-size operand: szbytes==0 -> zero-fill, no global traffic
    asm volatile("cp.async.cg.shared.global [%0], [%1], 16, %2;\n"
                 :: "r"(saddr), "l"(gptr), "r"(szbytes));
}
__device__ __forceinline__ void cp_commit() {
    asm volatile("cp.async.commit_group;\n");
}
template <int N>
__device__ __forceinline__ void cp_wait() {
    asm volatile("cp.async.wait_group %0;\n" :: "n"(N));
}

__global__ __launch_bounds__(NTHR, 7)
void kre_kernel(const int* __restrict__ context,
                const int* __restrict__ center,
                const float* __restrict__ W,
                float* __restrict__ out)
{
    // Staging ring: NW warps x S stages x 128 float4 (2 KB/row) = 24 KB.
    // Reused as the cross-warp accumulator buffer after the main loop.
    __shared__ float4 s_buf[NW * S * 128];
    __shared__ float  s_wsum[NW];
    __shared__ int    s_idx[CW];

    const int b    = blockIdx.x;
    const int tid  = threadIdx.x;
    const int lane = tid & 31;
    const int warp = tid >> 5;

    if (tid < CW) s_idx[tid] = context[b * CW + tid];
    __syncthreads();

    // Center row slice for this lane (registers, reused for all rows)
    const float4* cen_p = (const float4*)(W + (size_t)center[b] * DDIM) + lane;
    float4 cen[4];
    #pragma unroll
    for (int i = 0; i < 4; ++i) cen[i] = cen_p[i * 32];

    float4 acc[4];
    #pragma unroll
    for (int i = 0; i < 4; ++i) acc[i] = make_float4(0.f, 0.f, 0.f, 0.f);
    float wsum = 0.f;

    const unsigned int sbase =
        (unsigned int)__cvta_generic_to_shared(s_buf)
        + (unsigned int)(warp * S * 128) * 16u;

    // Each lane copies ONLY its own 4 chunks of each row, so per-thread
    // cp.async.wait_group ordering is sufficient — no barriers in the loop.
    auto issue_row = [&](int r, int sz) {
        const int  rc = (r < CPW) ? r : (CPW - 1);          // keep address valid
        const char* g = (const char*)(W + (size_t)s_idx[warp * CPW + rc] * DDIM)
                        + (size_t)lane * 16;
        const unsigned int dst = sbase + (unsigned int)((r % S) * 128 + lane) * 16u;
        #pragma unroll
        for (int i = 0; i < 4; ++i)
            cp16(dst + i * 32 * 16, g + i * 32 * 16, sz);
        cp_commit();
    };

    issue_row(0, 16);
    issue_row(1, 16);

    #pragma unroll
    for (int cc = 0; cc < CPW; ++cc) {
        // Keep the group stream uniform; tail issues are zero-fill (no traffic)
        issue_row(cc + 2, (cc + 2 < CPW) ? 16 : 0);
        cp_wait<2>();   // oldest outstanding group (row cc) complete

        const float4* vb = s_buf + (warp * S + (cc % S)) * 128 + lane;

        float d = 0.f;
        #pragma unroll
        for (int i = 0; i < 4; ++i) {
            const float4 v = vb[i * 32];
            const float dx = v.x - cen[i].x;
            const float dy = v.y - cen[i].y;
            const float dz = v.z - cen[i].z;
            const float dw = v.w - cen[i].w;
            d = fmaf(dx, dx, d);
            d = fmaf(dy, dy, d);
            d = fmaf(dz, dz, d);
            d = fmaf(dw, dw, d);
        }
        d += __shfl_xor_sync(0xffffffffu, d, 16);
        d += __shfl_xor_sync(0xffffffffu, d, 8);
        d += __shfl_xor_sync(0xffffffffu, d, 4);
        d += __shfl_xor_sync(0xffffffffu, d, 2);
        d += __shfl_xor_sync(0xffffffffu, d, 1);

        const float wgt = __expf(-0.5f * d);   // SIGMA = 1; exact 1.0 at d==0
        wsum += wgt;

        #pragma unroll
        for (int i = 0; i < 4; ++i) {
            const float4 v = vb[i * 32];       // SMEM re-read (cheap)
            acc[i].x = fmaf(wgt, v.x, acc[i].x);
            acc[i].y = fmaf(wgt, v.y, acc[i].y);
            acc[i].z = fmaf(wgt, v.z, acc[i].z);
            acc[i].w = fmaf(wgt, v.w, acc[i].w);
        }
    }

    // All warps done with the staging ring -> reuse it for the combine.
    __syncthreads();
    float* s_acc = (float*)s_buf;              // needs 8 KB of the 24 KB ring

    #pragma unroll
    for (int i = 0; i < 4; ++i)
        *(float4*)(s_acc + warp * DDIM + i * 128 + lane * 4) = acc[i];
    if (lane == 0) s_wsum[warp] = wsum;        // wgt broadcast => lane-uniform
    __syncthreads();

    // Combine 4 warp partials; normalize once at the end (same math as ref)
    const float inv = 1.0f / (s_wsum[0] + s_wsum[1] + s_wsum[2] + s_wsum[3] + 1e-8f);

    float4 r = make_float4(0.f, 0.f, 0.f, 0.f);
    #pragma unroll
    for (int w = 0; w < NW; ++w) {
        const float4 p = *(const float4*)(s_acc + w * DDIM + tid * 4);
        r.x += p.x; r.y += p.y; r.z += p.z; r.w += p.w;
    }
    r.x *= inv; r.y *= inv; r.z *= inv; r.w *= inv;
    *(float4*)(out + (size_t)b * DDIM + tid * 4) = r;
}

extern "C" void kernel_launch(void* const* d_in, const int* in_sizes, int n_in,
                              void* d_out, int out_size)
{
    const int*   context = (const int*)d_in[0];   // [B, C] int32
    const int*   center  = (const int*)d_in[1];   // [B]    int32
    const float* W       = (const float*)d_in[2]; // [V, D] float32
    float*       out     = (float*)d_out;         // [B, D] float32

    const int B = in_sizes[1];                    // 8192

    kre_kernel<<<B, NTHR>>>(context, center, W, out);
}

// round 13
// speedup vs baseline: 1.4219x; 1.3822x over previous
#include <cuda_runtime.h>
#include <cuda_bf16.h>
#include <cstdint>

#define CW    32            // context window
#define DDIM  512           // embedding dim
#define NTHR  128           // 4 warps per CTA, one CTA per batch row
#define NW    4             // warps per CTA
#define CPW   (CW / NW)     // context rows per warp = 8

typedef unsigned long long u64;

// Packed 2xfp32 ops — sm_103a only emits these from explicit PTX.
__device__ __forceinline__ u64 add2(u64 a, u64 b) {
    u64 r; asm("add.rn.f32x2 %0, %1, %2;" : "=l"(r) : "l"(a), "l"(b)); return r;
}
__device__ __forceinline__ u64 fma2(u64 a, u64 b, u64 c) {
    u64 r; asm("fma.rn.f32x2 %0, %1, %2, %3;" : "=l"(r) : "l"(a), "l"(b), "l"(c)); return r;
}

// Lane l owns dims { i*128 + l*4 .. +4 } for i in 0..3  (coalesced, conflict-free)

__global__ __launch_bounds__(NTHR, 6)
void kre_kernel(const int* __restrict__ context,
                const int* __restrict__ center,
                const float* __restrict__ W,
                float* __restrict__ out)
{
    __shared__ float s_acc[NW * DDIM];   // per-warp partial outputs (8 KB)
    __shared__ float s_wsum[NW];
    __shared__ int   s_idx[CW];

    const int b    = blockIdx.x;
    const int tid  = threadIdx.x;
    const int lane = tid & 31;
    const int warp = tid >> 5;

    if (tid < CW) s_idx[tid] = context[b * CW + tid];
    __syncthreads();

    // Center slice, pre-negated (sign-flip both packed halves) so the
    // distance diff is a single packed ADD2 per pair.
    const ulonglong2* cen_p = (const ulonglong2*)(W + (size_t)center[b] * DDIM) + lane;
    u64 ncen[8];
    #pragma unroll
    for (int i = 0; i < 4; ++i) {
        const ulonglong2 t = cen_p[i * 32];
        ncen[2*i]   = t.x ^ 0x8000000080000000ULL;
        ncen[2*i+1] = t.y ^ 0x8000000080000000ULL;
    }

    u64 acc[8];
    #pragma unroll
    for (int i = 0; i < 8; ++i) acc[i] = 0ULL;   // packed {0,0}
    float wsum = 0.f;

    // Each warp: 8 context rows, single pass, all math in packed f32x2.
    #pragma unroll
    for (int cc = 0; cc < CPW; ++cc) {
        const ulonglong2* p =
            (const ulonglong2*)(W + (size_t)s_idx[warp * CPW + cc] * DDIM) + lane;
        ulonglong2 v[4];
        #pragma unroll
        for (int i = 0; i < 4; ++i) v[i] = p[i * 32];

        // Squared distance: 8 ADD2 + 8 FMA2 (two accumulators to shorten chain)
        u64 dd0 = 0ULL, dd1 = 0ULL;
        #pragma unroll
        for (int i = 0; i < 4; ++i) {
            const u64 e0 = add2(v[i].x, ncen[2*i]);
            dd0 = fma2(e0, e0, dd0);
            const u64 e1 = add2(v[i].y, ncen[2*i+1]);
            dd1 = fma2(e1, e1, dd1);
        }
        const u64 dd = add2(dd0, dd1);
        float lo, hi;
        asm("mov.b64 {%0, %1}, %2;" : "=f"(lo), "=f"(hi) : "l"(dd));
        float d = lo + hi;
        d += __shfl_xor_sync(0xffffffffu, d, 16);
        d += __shfl_xor_sync(0xffffffffu, d, 8);
        d += __shfl_xor_sync(0xffffffffu, d, 4);
        d += __shfl_xor_sync(0xffffffffu, d, 2);
        d += __shfl_xor_sync(0xffffffffu, d, 1);

        const float wgt = __expf(-0.5f * d);     // SIGMA = 1; exact 1.0 at d==0
        wsum += wgt;

        u64 w2;
        asm("mov.b64 %0, {%1, %1};" : "=l"(w2) : "f"(wgt));
        #pragma unroll
        for (int i = 0; i < 4; ++i) {
            acc[2*i]   = fma2(w2, v[i].x, acc[2*i]);
            acc[2*i+1] = fma2(w2, v[i].y, acc[2*i+1]);
        }
    }

    // Spill per-warp partials (lane stride 16 B -> conflict-free)
    #pragma unroll
    for (int i = 0; i < 4; ++i) {
        ulonglong2 t;
        t.x = acc[2*i];
        t.y = acc[2*i+1];
        *(ulonglong2*)(s_acc + warp * DDIM + i * 128 + lane * 4) = t;
    }
    if (lane == 0) s_wsum[warp] = wsum;          // butterfly => lane-uniform
    __syncthreads();

    // Combine 4 warp partials; normalize once at the end (same math as ref)
    const float inv = 1.0f / (s_wsum[0] + s_wsum[1] + s_wsum[2] + s_wsum[3] + 1e-8f);

    float4 r = make_float4(0.f, 0.f, 0.f, 0.f);
    #pragma unroll
    for (int w = 0; w < NW; ++w) {
        const float4 p = *(const float4*)(s_acc + w * DDIM + tid * 4);
        r.x += p.x; r.y += p.y; r.z += p.z; r.w += p.w;
    }
    r.x *= inv; r.y *= inv; r.z *= inv; r.w *= inv;
    *(float4*)(out + (size_t)b * DDIM + tid * 4) = r;
}

extern "C" void kernel_launch(void* const* d_in, const int* in_sizes, int n_in,
                              void* d_out, int out_size)
{
    const int*   context = (const int*)d_in[0];   // [B, C] int32
    const int*   center  = (const int*)d_in[1];   // [B]    int32
    const float* W       = (const float*)d_in[2]; // [V, D] float32
    float*       out     = (float*)d_out;         // [B, D] float32

    const int B = in_sizes[1];                    // 8192

    kre_kernel<<<B, NTHR>>>(context, center, W, out);
}

// round 14
// speedup vs baseline: 1.4245x; 1.0018x over previous
#include <cuda_runtime.h>
#include <cuda_bf16.h>
#include <cstdint>

#define CW    32            // context window
#define DDIM  512           // embedding dim
#define NTHR  128           // 4 warps per CTA, one CTA per batch row
#define NW    4             // warps per CTA
#define CPW   (CW / NW)     // context rows per warp = 8

typedef unsigned long long u64;

// Packed 2xfp32 ops — sm_103a only emits these from explicit PTX.
__device__ __forceinline__ u64 add2(u64 a, u64 b) {
    u64 r; asm("add.rn.f32x2 %0, %1, %2;" : "=l"(r) : "l"(a), "l"(b)); return r;
}
__device__ __forceinline__ u64 fma2(u64 a, u64 b, u64 c) {
    u64 r; asm("fma.rn.f32x2 %0, %1, %2, %3;" : "=l"(r) : "l"(a), "l"(b), "l"(c)); return r;
}
// Opaque 16B shared load: volatile asm so the unrolled loop CANNOT hoist/CSE
// the center row back into registers (that would re-inflate regs to 80).
__device__ __forceinline__ void lds_v2u64(unsigned int addr, u64& a, u64& b) {
    asm volatile("ld.shared.v2.u64 {%0, %1}, [%2];" : "=l"(a), "=l"(b) : "r"(addr));
}

// Lane l owns dims { i*128 + l*4 .. +4 } for i in 0..3  (coalesced, conflict-free)

__global__ __launch_bounds__(NTHR, 8)
void kre_kernel(const int* __restrict__ context,
                const int* __restrict__ center,
                const float* __restrict__ W,
                float* __restrict__ out)
{
    __shared__ float s_acc[NW * DDIM];   // per-warp partial outputs (8 KB)
    __shared__ float s_ncen[DDIM];       // negated center row (2 KB, CTA-shared)
    __shared__ float s_wsum[NW];
    __shared__ int   s_idx[CW];

    const int b    = blockIdx.x;
    const int tid  = threadIdx.x;
    const int lane = tid & 31;
    const int warp = tid >> 5;

    if (tid < CW) s_idx[tid] = context[b * CW + tid];

    // Build negated center ONCE per CTA in SMEM (one copy instead of 16 regs
    // per thread). Each thread handles its 4 floats; coalesced LDG.
    {
        const float4 c = *(const float4*)(W + (size_t)center[b] * DDIM + tid * 4);
        float4 n; n.x = -c.x; n.y = -c.y; n.z = -c.z; n.w = -c.w;
        *(float4*)(s_ncen + tid * 4) = n;
    }
    __syncthreads();

    const unsigned int ncen_base =
        (unsigned int)__cvta_generic_to_shared(s_ncen) + (unsigned int)lane * 16u;

    u64 acc[8];
    #pragma unroll
    for (int i = 0; i < 8; ++i) acc[i] = 0ULL;   // packed {0,0}
    float wsum = 0.f;

    // Each warp: 8 context rows, single pass, all math in packed f32x2.
    #pragma unroll
    for (int cc = 0; cc < CPW; ++cc) {
        const ulonglong2* p =
            (const ulonglong2*)(W + (size_t)s_idx[warp * CPW + cc] * DDIM) + lane;
        ulonglong2 v[4];
        #pragma unroll
        for (int i = 0; i < 4; ++i) v[i] = p[i * 32];

        // Squared distance: 8 ADD2 + 8 FMA2 (two accumulators shorten chain);
        // center chunks re-read from SMEM each row (cheap LDS, zero residency)
        u64 dd0 = 0ULL, dd1 = 0ULL;
        #pragma unroll
        for (int i = 0; i < 4; ++i) {
            u64 nc0, nc1;
            lds_v2u64(ncen_base + (unsigned int)(i * 512), nc0, nc1);
            const u64 e0 = add2(v[i].x, nc0);
            dd0 = fma2(e0, e0, dd0);
            const u64 e1 = add2(v[i].y, nc1);
            dd1 = fma2(e1, e1, dd1);
        }
        const u64 dd = add2(dd0, dd1);
        float lo, hi;
        asm("mov.b64 {%0, %1}, %2;" : "=f"(lo), "=f"(hi) : "l"(dd));
        float d = lo + hi;
        d += __shfl_xor_sync(0xffffffffu, d, 16);
        d += __shfl_xor_sync(0xffffffffu, d, 8);
        d += __shfl_xor_sync(0xffffffffu, d, 4);
        d += __shfl_xor_sync(0xffffffffu, d, 2);
        d += __shfl_xor_sync(0xffffffffu, d, 1);

        const float wgt = __expf(-0.5f * d);     // SIGMA = 1; exact 1.0 at d==0
        wsum += wgt;

        u64 w2;
        asm("mov.b64 %0, {%1, %1};" : "=l"(w2) : "f"(wgt));
        #pragma unroll
        for (int i = 0; i < 4; ++i) {
            acc[2*i]   = fma2(w2, v[i].x, acc[2*i]);
            acc[2*i+1] = fma2(w2, v[i].y, acc[2*i+1]);
        }
    }

    // Spill per-warp partials (lane stride 16 B -> conflict-free)
    #pragma unroll
    for (int i = 0; i < 4; ++i) {
        ulonglong2 t;
        t.x = acc[2*i];
        t.y = acc[2*i+1];
        *(ulonglong2*)(s_acc + warp * DDIM + i * 128 + lane * 4) = t;
    }
    if (lane == 0) s_wsum[warp] = wsum;          // butterfly => lane-uniform
    __syncthreads();

    // Combine 4 warp partials; normalize once at the end (same math as ref)
    const float inv = 1.0f / (s_wsum[0] + s_wsum[1] + s_wsum[2] + s_wsum[3] + 1e-8f);

    float4 r = make_float4(0.f, 0.f, 0.f, 0.f);
    #pragma unroll
    for (int w = 0; w < NW; ++w) {
        const float4 p = *(const float4*)(s_acc + w * DDIM + tid * 4);
        r.x += p.x; r.y += p.y; r.z += p.z; r.w += p.w;
    }
    r.x *= inv; r.y *= inv; r.z *= inv; r.w *= inv;
    *(float4*)(out + (size_t)b * DDIM + tid * 4) = r;
}

extern "C" void kernel_launch(void* const* d_in, const int* in_sizes, int n_in,
                              void* d_out, int out_size)
{
    const int*   context = (const int*)d_in[0];   // [B, C] int32
    const int*   center  = (const int*)d_in[1];   // [B]    int32
    const float* W       = (const float*)d_in[2]; // [V, D] float32
    float*       out     = (float*)d_out;         // [B, D] float32

    const int B = in_sizes[1];                    // 8192

    kre_kernel<<<B, NTHR>>>(context, center, W, out);
}